// round 17
// baseline (speedup 1.0000x reference)
#include <cuda_runtime.h>
#include <cstdint>
#include <cstddef>

// Problem shapes (fixed by the dataset)
#define NB 64          // batch
#define NL 512         // sequence length
#define ND 50          // embedding dim
#define NDP 52         // padded dim (even, float4-friendly)
#define NM 128         // number of measurement kernels
#define LCHUNK 64      // tokens per k_main CTA
#define NCHUNK (NL / LCHUNK)   // 8
#define TROW (2 * NDP) // floats per token row in g_v: vr[52] | vi[52] = 104
#define SVLD 66        // padded floats per d-row in smem (bank spread)
#define NGATHER (NB * NL / 8)  // 4096 gather CTAs

// ---------------- device-global scratch (no runtime allocation) ----------------
__device__ float g_sw[NB * NL];                   // sqrt(exp(mix)) per token
__device__ float g_einv[NB];                      // 1 / sum_l exp(mix) per batch
// pre-splatted kernel rows: entry [d][j][g] = (k[m,d], k[m,d]) packed, m = 4g+j
__device__ unsigned long long g_ksA[ND * 4 * 32]; // kr_n splats
__device__ unsigned long long g_ksB[ND * 4 * 32]; // ki_n splats
__device__ __align__(16) float4 g_v4[(size_t)NB * NL * TROW / 4]; // scaled vr|vi (~13.6MB)

// packed f32x2 helpers (Blackwell sm_103a)
__device__ __forceinline__ float2 up2(unsigned long long v) {
    float2 r;
    asm("mov.b64 {%0, %1}, %2;" : "=f"(r.x), "=f"(r.y) : "l"(v));
    return r;
}
#define FMA2(d, a, b) asm("fma.rn.f32x2 %0, %1, %2, %0;" : "+l"(d) : "l"(a), "l"(b))

__device__ __forceinline__ unsigned long long splat2(float a) {
    unsigned int u = __float_as_uint(a);
    return ((unsigned long long)u << 32) | (unsigned long long)u;
}

// ---------------- K0: per-batch softmax denominators (softmax only) ----------------
__global__ void __launch_bounds__(512) k_prep(const int* __restrict__ x,
                                              const float* __restrict__ mix) {
    int b = blockIdx.x;
    int t = threadIdx.x;

    // softmax numerator without max-shift: mix ~ N(0,1), exp is safe in fp32
    float e = __expf(mix[x[b * NL + t]]);

    __shared__ float red[16];
    float s = e;
#pragma unroll
    for (int o = 16; o > 0; o >>= 1) s += __shfl_xor_sync(0xffffffffu, s, o);
    if ((t & 31) == 0) red[t >> 5] = s;
    __syncthreads();
    if (t < 16) {
        float ss = red[t];
#pragma unroll
        for (int o = 8; o > 0; o >>= 1) ss += __shfl_xor_sync(0x0000ffffu, ss, o);
        if (t == 0) g_einv[b] = 1.f / ss;
    }
    g_sw[b * NL + t] = sqrtf(e);
}

// ---------------- K1: gather/convert + (one extra block) splat-table build ----------------
// blocks 0..NGATHER-1: one warp per token, v = sqrt(e)*amp*exp(i*pha) -> g_v.
// block NGATHER: normalize measurement kernels and build splat tables.
__global__ void __launch_bounds__(256) k_gather(const int* __restrict__ x,
                                                const float* __restrict__ amp,
                                                const float* __restrict__ pha,
                                                const float* __restrict__ kr,
                                                const float* __restrict__ ki) {
    int t = threadIdx.x;

    if (blockIdx.x == NGATHER) {
        // ---- splat-table builder ----
        __shared__ float rn_s[NM];
        if (t < NM) {
            float s = 0.f;
#pragma unroll 2
            for (int d = 0; d < ND; d++) {
                float a = kr[t * ND + d];
                float c = ki[t * ND + d];
                s = fmaf(a, a, s);
                s = fmaf(c, c, s);
            }
            rn_s[t] = rsqrtf(s);
        }
        __syncthreads();
#pragma unroll 1
        for (int idx = t; idx < NM * ND; idx += 256) {
            int m = idx / ND;
            int d = idx % ND;
            float rn = rn_s[m];
            int g = m >> 2, j = m & 3;
            int pos = (d * 4 + j) * 32 + g;
            g_ksA[pos] = splat2(kr[m * ND + d] * rn);
            g_ksB[pos] = splat2(ki[m * ND + d] * rn);
        }
        return;
    }

    // ---- gather: one warp per token ----
    int tok  = blockIdx.x * 8 + (t >> 5);
    int lane = t & 31;

    int idx  = x[tok];
    float sw = g_sw[tok];

    const float* a_ = amp + (size_t)idx * ND;
    const float* p_ = pha + (size_t)idx * ND;
    float* dst = (float*)g_v4 + (size_t)tok * TROW;

    float a0 = a_[lane];
    float p0 = p_[lane];

    float s, c;
    __sincosf(p0, &s, &c);
    float amp0 = a0 * sw;
    dst[lane]       = amp0 * c;
    dst[NDP + lane] = amp0 * s;

    if (lane < NDP - 32) {                 // lanes 0..19 cover d=32..51
        float vr1 = 0.f, vi1 = 0.f;
        if (lane < ND - 32) {              // lanes 0..17: real data d=32..49
            float a1 = a_[lane + 32];
            float p1 = p_[lane + 32];
            __sincosf(p1, &s, &c);
            float amp1 = a1 * sw;
            vr1 = amp1 * c;
            vi1 = amp1 * s;
        }
        dst[32 + lane]       = vr1;        // d=50,51 -> zeros
        dst[NDP + 32 + lane] = vi1;
    }
}

// ---------------- K2: main contraction (register-tiled outer product) ----------------
// CTA = 256 thr (8 warps), tile = 64 tokens x 128 m. Thread (lane g, warp w) owns
// m = 4g+j (j=0..3) and token-pairs pp = 4w+jj (jj=0..3): 32 packed accumulators.
// Per dim d: 8 broadcast LDS.64 (v pairs, warp-uniform), 8 LDG.64 splats (L1-resident
// table, lane-strided conflict-free), 8 LOP3 (packed -vr), 64 FMA2. NO shuffles.
//   ar[m,pp] += kr_m (x) vr_pp + ki_m (x) vi_pp
//   ai[m,pp] += kr_m (x) vi_pp + ki_m (x) (-vr_pp)
// Epilogue: s_m = sum(ar^2+ai^2) over pairs+halves -> smem partials -> one
// atomicAdd per m per CTA, scaled by 1/sum(e).
__global__ void __launch_bounds__(256, 2) k_main(float* __restrict__ out) {
    __shared__ float svr[NDP * SVLD];     // 52*66*4 = 13728 B
    __shared__ float svi[NDP * SVLD];
    __shared__ float spart[8 * NM];       // per-warp partials, 4 KB

    int b = blockIdx.x >> 3;     // / NCHUNK
    int c = blockIdx.x & 7;      // % NCHUNK
    int t = threadIdx.x;
    int lane = t & 31;           // m-group g
    int w = t >> 5;              // warp -> token-pair group

    // ---- stage token tile, transposing to [d][token] layout ----
    {
        const float4* src = g_v4 + (size_t)(b * NL + c * LCHUNK) * (TROW / 4);
#pragma unroll 1
        for (int idx = t; idx < LCHUNK * (TROW / 4); idx += 256) {
            int tt = idx / (TROW / 4);        // token 0..63
            int q  = idx % (TROW / 4);        // float4 index 0..25
            float4 v = src[idx];
            float* dstbase = (q < (NDP / 4)) ? svr : svi;
            int d0 = (q % (NDP / 4)) * 4;
            dstbase[(d0 + 0) * SVLD + tt] = v.x;
            dstbase[(d0 + 1) * SVLD + tt] = v.y;
            dstbase[(d0 + 2) * SVLD + tt] = v.z;
            dstbase[(d0 + 3) * SVLD + tt] = v.w;
        }
    }
    __syncthreads();

    unsigned long long ar[4][4] = {}, ai[4][4] = {};  // [j][jj]
    const unsigned long long SGN = 0x8000000080000000ull;

#pragma unroll 1
    for (int d = 0; d < ND; d++) {
        // token-pair operands: warp-uniform broadcast LDS.64
        const float* br = svr + d * SVLD + 8 * w;   // pair pp=4w+jj -> float off 2pp
        const float* bi = svi + d * SVLD + 8 * w;
        unsigned long long vr[4], vi[4], vn[4];
#pragma unroll
        for (int jj = 0; jj < 4; jj++) {
            vr[jj] = *(const unsigned long long*)(br + 2 * jj);
            vi[jj] = *(const unsigned long long*)(bi + 2 * jj);
            vn[jj] = vr[jj] ^ SGN;                  // packed -vr (ALU pipe)
        }
        // kernel splats: lane-strided LDG.64 from L1-resident table
        unsigned long long ka[4], kb[4];
#pragma unroll
        for (int j = 0; j < 4; j++) {
            ka[j] = __ldg(&g_ksA[(d * 4 + j) * 32 + lane]);
            kb[j] = __ldg(&g_ksB[(d * 4 + j) * 32 + lane]);
        }
#pragma unroll
        for (int j = 0; j < 4; j++) {
#pragma unroll
            for (int jj = 0; jj < 4; jj++) {
                FMA2(ar[j][jj], ka[j], vr[jj]);
                FMA2(ar[j][jj], kb[j], vi[jj]);
                FMA2(ai[j][jj], ka[j], vi[jj]);
                FMA2(ai[j][jj], kb[j], vn[jj]);
            }
        }
    }

    // ---- epilogue: square-sum over pairs & halves ----
#pragma unroll
    for (int j = 0; j < 4; j++) {
        float s = 0.f;
#pragma unroll
        for (int jj = 0; jj < 4; jj++) {
            float2 a = up2(ar[j][jj]);
            float2 q = up2(ai[j][jj]);
            s = fmaf(a.x, a.x, s);
            s = fmaf(a.y, a.y, s);
            s = fmaf(q.x, q.x, s);
            s = fmaf(q.y, q.y, s);
        }
        spart[w * NM + (lane * 4 + j)] = s;   // m = 4*lane + j
    }
    __syncthreads();

    if (t < NM) {
        float s = 0.f;
#pragma unroll
        for (int ww = 0; ww < 8; ww++) s += spart[ww * NM + t];
        atomicAdd(&out[b * NM + t], s * g_einv[b]);
    }
}

// ---------------- entry point ----------------
extern "C" void kernel_launch(void* const* d_in, const int* in_sizes, int n_in,
                              void* d_out, int out_size) {
    const int*   x   = (const int*)  d_in[0];   // [B, L] int32
    const float* amp = (const float*)d_in[1];   // [VOCAB, D]
    const float* pha = (const float*)d_in[2];   // [VOCAB, D]
    const float* mix = (const float*)d_in[3];   // [VOCAB, 1]
    const float* kr  = (const float*)d_in[4];   // [M, D]
    const float* ki  = (const float*)d_in[5];   // [M, D]
    float* out = (float*)d_out;                 // [B, M]

    cudaMemsetAsync(out, 0, (size_t)NB * NM * sizeof(float));
    k_prep<<<NB, NL>>>(x, mix);
    k_gather<<<NGATHER + 1, 256>>>(x, amp, pha, kr, ki);  // +1 block builds splat tables
    k_main<<<NB * NCHUNK, 256>>>(out);
}